// round 2
// baseline (speedup 1.0000x reference)
#include <cuda_runtime.h>
#include <cstdint>

// Problem constants
#define B_  8
#define N_  2048
#define FIN 256
#define FOUT 64

// Scratch (device globals: allocation-free)
__device__ float g_Wh[B_ * N_ * FOUT];   // 4 MB
__device__ float g_Wh1[B_ * N_];
__device__ float g_Wh2[B_ * N_];
__device__ float g_maxWh2[B_];

// ---------------------------------------------------------------------------
// K0: Wh = h @ W.   Grid: (B*N/64) blocks of 256 threads, 64 rows per block.
// Thread (tx = col 0..63, ty = 0..3) computes rows ty+4i, i=0..15, col tx.
// ---------------------------------------------------------------------------
__global__ void k_gemm1(const float* __restrict__ h, const float* __restrict__ W) {
    __shared__ __align__(16) float hs[64][64];    // h tile  [row][k]
    __shared__ __align__(16) float Wst[64][68];   // W tile transposed [col][k], padded

    int tid = threadIdx.x;
    int tx = tid & 63, ty = tid >> 6;
    int r0 = blockIdx.x * 64;

    float acc[16];
#pragma unroll
    for (int i = 0; i < 16; i++) acc[i] = 0.f;

    for (int kt = 0; kt < 4; kt++) {
        __syncthreads();
#pragma unroll
        for (int l = 0; l < 16; l++) {
            int idx = l * 256 + tid;
            int r = idx >> 6, kk = idx & 63;
            hs[r][kk] = h[(size_t)(r0 + r) * FIN + kt * 64 + kk];
            // W tile: read coalesced W[k][c], write transposed
            Wst[kk /*c*/ == kk ? (idx & 63) : 0][idx >> 6] = 0.f; // placeholder avoided below
        }
        // (re-do W load cleanly; the line above is dead-stored by this loop)
#pragma unroll
        for (int l = 0; l < 16; l++) {
            int idx = l * 256 + tid;
            int kk = idx >> 6, c = idx & 63;
            Wst[c][kk] = W[(size_t)(kt * 64 + kk) * FOUT + c];
        }
        __syncthreads();

        for (int kk = 0; kk < 64; kk += 4) {
            float4 wv = *(const float4*)&Wst[tx][kk];
#pragma unroll
            for (int i = 0; i < 16; i++) {
                float4 hv = *(const float4*)&hs[ty + 4 * i][kk];
                acc[i] += hv.x * wv.x;
                acc[i] += hv.y * wv.y;
                acc[i] += hv.z * wv.z;
                acc[i] += hv.w * wv.w;
            }
        }
    }
#pragma unroll
    for (int i = 0; i < 16; i++)
        g_Wh[(size_t)(r0 + ty + 4 * i) * FOUT + tx] = acc[i];
}

// ---------------------------------------------------------------------------
// K0b: Wh1[r] = Wh[r,:]·a[0:64],  Wh2[r] = Wh[r,:]·a[64:128]
// One warp per 32 rows. Grid 64 x 256.
// ---------------------------------------------------------------------------
__global__ void k_rowproj(const float* __restrict__ a) {
    int tid = threadIdx.x;
    int lane = tid & 31;
    int warp_g = blockIdx.x * 8 + (tid >> 5);   // 512 warps, 32 rows each

    float a0l = a[lane], a0h = a[lane + 32];
    float a1l = a[64 + lane], a1h = a[96 + lane];

    int row0 = warp_g * 32;
    for (int r = 0; r < 32; r++) {
        int row = row0 + r;
        float wl = g_Wh[(size_t)row * FOUT + lane];
        float wh = g_Wh[(size_t)row * FOUT + lane + 32];
        float s1 = wl * a0l + wh * a0h;
        float s2 = wl * a1l + wh * a1h;
#pragma unroll
        for (int d = 16; d > 0; d >>= 1) {
            s1 += __shfl_xor_sync(0xffffffffu, s1, d);
            s2 += __shfl_xor_sync(0xffffffffu, s2, d);
        }
        if (lane == 0) {
            g_Wh1[row] = s1;
            g_Wh2[row] = s2;
        }
    }
}

// ---------------------------------------------------------------------------
// K0c: per-batch max of Wh2.  8 blocks x 256 threads.
// ---------------------------------------------------------------------------
__global__ void k_maxwh2() {
    __shared__ float red[256];
    int b = blockIdx.x;
    float m = -1e30f;
    for (int i = threadIdx.x; i < N_; i += 256)
        m = fmaxf(m, g_Wh2[(size_t)b * N_ + i]);
    red[threadIdx.x] = m;
    __syncthreads();
    for (int s = 128; s > 0; s >>= 1) {
        if (threadIdx.x < s) red[threadIdx.x] = fmaxf(red[threadIdx.x], red[threadIdx.x + s]);
        __syncthreads();
    }
    if (threadIdx.x == 0) g_maxWh2[b] = red[0];
}

// ---------------------------------------------------------------------------
// K1: fused masked-softmax attention + PV product + ELU.
// Grid: 512 blocks (8 batches x 64 row-tiles of 32 rows), 256 threads.
// Single-pass softmax with analytic per-row max bound:
//   M_i = leaky(Wh1_i + max_j Wh2_j)  >=  max over masked j of e_ij.
// Per 64-wide j chunk:
//   phase1: P[32][64] = adj ? exp(leaky(Wh1_i+Wh2_j) - M_i) : 0, lane-partial l
//   phase2: acc[32][64] += P @ WhTile  (register-blocked fp32)
// ---------------------------------------------------------------------------
__global__ void k_attn(const int* __restrict__ adj, float* __restrict__ out) {
    __shared__ __align__(16) float Whs[64][68];   // Wh j-tile [j][c], padded
    __shared__ float Ps[32][64];                  // P tile   [row][j]
    __shared__ float wh1s[32], Mr[32], ls[32], Wh2s[64];

    int tid = threadIdx.x;
    int b  = blockIdx.x >> 6;
    int i0 = (blockIdx.x & 63) * 32;
    size_t rowbase = (size_t)b * N_ + i0;

    if (tid < 32) {
        float w1 = g_Wh1[rowbase + tid];
        wh1s[tid] = w1;
        float s = w1 + g_maxWh2[b];
        Mr[tid] = s > 0.f ? s : 0.2f * s;
        ls[tid] = 0.f;
    }

    float acc0[4] = {0.f, 0.f, 0.f, 0.f};
    float acc1[4] = {0.f, 0.f, 0.f, 0.f};
    float lp[8]   = {0.f, 0.f, 0.f, 0.f, 0.f, 0.f, 0.f, 0.f};

    int jx = tid & 63, ry = tid >> 6;     // phase-1 mapping
    int cx = tid & 15, cy = tid >> 4;     // phase-2 mapping: rows cy, cy+16; cols 4cx..4cx+3
    const int* adjrow0 = adj + rowbase * N_;

    for (int jt = 0; jt < N_; jt += 64) {
        __syncthreads();   // previous phase2 done before overwriting tiles
#pragma unroll
        for (int l = 0; l < 16; l++) {
            int idx = l * 256 + tid;
            int j = idx >> 6, c = idx & 63;
            Whs[j][c] = g_Wh[((size_t)b * N_ + jt + j) * FOUT + c];
        }
        if (tid < 64) Wh2s[tid] = g_Wh2[(size_t)b * N_ + jt + tid];
        __syncthreads();

        // ---- phase 1: attention probabilities ----
        {
            float wh2v = Wh2s[jx];
#pragma unroll
            for (int k = 0; k < 8; k++) {
                int row = ry + 4 * k;
                float s = wh1s[row] + wh2v;
                float e = s > 0.f ? s : 0.2f * s;
                int av = adjrow0[(size_t)row * N_ + jt + jx];
                float p = (av > 0) ? __expf(e - Mr[row]) : 0.f;
                Ps[row][jx] = p;
                lp[k] += p;
            }
        }
        __syncthreads();

        // ---- phase 2: acc += P @ WhTile ----
#pragma unroll 8
        for (int kk = 0; kk < 64; kk++) {
            float4 wv = *(const float4*)&Whs[kk][4 * cx];
            float p0 = Ps[cy][kk];
            float p1 = Ps[cy + 16][kk];
            acc0[0] += p0 * wv.x; acc0[1] += p0 * wv.y;
            acc0[2] += p0 * wv.z; acc0[3] += p0 * wv.w;
            acc1[0] += p1 * wv.x; acc1[1] += p1 * wv.y;
            acc1[2] += p1 * wv.z; acc1[3] += p1 * wv.w;
        }
    }

    // ---- reduce lane-partial denominators into ls ----
#pragma unroll
    for (int k = 0; k < 8; k++) {
        float v = lp[k];
        v += __shfl_xor_sync(0xffffffffu, v, 16);
        v += __shfl_xor_sync(0xffffffffu, v, 8);
        v += __shfl_xor_sync(0xffffffffu, v, 4);
        v += __shfl_xor_sync(0xffffffffu, v, 2);
        v += __shfl_xor_sync(0xffffffffu, v, 1);
        if ((tid & 31) == 0) atomicAdd(&ls[ry + 4 * k], v);
    }
    __syncthreads();

    // ---- epilogue: normalize + ELU + store ----
    {
        float inv0 = 1.f / ls[cy];
        float inv1 = 1.f / ls[cy + 16];
        float4 o0, o1;
        float v;
        v = acc0[0] * inv0; o0.x = v > 0.f ? v : expm1f(v);
        v = acc0[1] * inv0; o0.y = v > 0.f ? v : expm1f(v);
        v = acc0[2] * inv0; o0.z = v > 0.f ? v : expm1f(v);
        v = acc0[3] * inv0; o0.w = v > 0.f ? v : expm1f(v);
        v = acc1[0] * inv1; o1.x = v > 0.f ? v : expm1f(v);
        v = acc1[1] * inv1; o1.y = v > 0.f ? v : expm1f(v);
        v = acc1[2] * inv1; o1.z = v > 0.f ? v : expm1f(v);
        v = acc1[3] * inv1; o1.w = v > 0.f ? v : expm1f(v);
        *(float4*)(out + (rowbase + cy) * FOUT + 4 * cx) = o0;
        *(float4*)(out + (rowbase + cy + 16) * FOUT + 4 * cx) = o1;
    }
}

// ---------------------------------------------------------------------------
extern "C" void kernel_launch(void* const* d_in, const int* in_sizes, int n_in,
                              void* d_out, int out_size) {
    const float* h   = (const float*)d_in[0];
    const int*   adj = (const int*)d_in[1];
    const float* W   = (const float*)d_in[2];
    const float* a   = (const float*)d_in[3];
    float* out = (float*)d_out;

    k_gemm1<<<(B_ * N_) / 64, 256>>>(h, W);
    k_rowproj<<<64, 256>>>(a);
    k_maxwh2<<<B_, 256>>>();
    k_attn<<<(B_ * N_) / 32, 256>>>(adj, out);
}